// round 3
// baseline (speedup 1.0000x reference)
#include <cuda_runtime.h>

#define D 128
#define MAX_NODES 100000
#define NT 64   // nodes per GEMM block

// Scratch (allocation-free rule: __device__ globals)
__device__ float g_Wt[D * 2 * D];                    // [k][jj]: jj<128 -> u-weights, jj>=128 -> v-weights
__device__ float g_u[(size_t)MAX_NODES * D];         // u[n] = A x[n]
__device__ float g_v[(size_t)MAX_NODES * D];         // v[n] = B x[n]
__device__ int   g_idx_is64;                         // 1 if edge_index buffer is int64, 0 if int32

// ---------------------------------------------------------------------------
// Sniff index dtype: if the buffer is int64 (values < 2^31, non-negative),
// every odd int32 word is zero. If int32, odd words are arbitrary node ids.
// ---------------------------------------------------------------------------
__global__ void sniff_idx_kernel(const int* __restrict__ idx32, int n_words) {
    int all_zero = 1;
    for (int i = 1; i < 128 && i < n_words; i += 2)
        if (idx32[i] != 0) { all_zero = 0; break; }
    g_idx_is64 = all_zero;
}

// ---------------------------------------------------------------------------
// Transpose W1 [128 out, 256 in] row-major into k-major g_Wt[k][jj]:
// jj in [0,128):   g_Wt[k*256+jj] = W1[jj][k]          (A part -> u)
// jj in [128,256): g_Wt[k*256+jj] = W1[jj-128][128+k]  (B part -> v)
// ---------------------------------------------------------------------------
__global__ void transpose_W_kernel(const float* __restrict__ W1) {
    int i = blockIdx.x * blockDim.x + threadIdx.x;
    if (i < D * 2 * D) {
        int k    = i >> 8;       // 0..127
        int jj   = i & 255;      // 0..255
        int j    = jj & 127;
        int half = jj >> 7;      // 0 = A, 1 = B
        g_Wt[i] = W1[j * 256 + half * 128 + k];
    }
}

// ---------------------------------------------------------------------------
// Node GEMM: u[n][j] = sum_k x[n][k]*W1[j][k], v[n][j] = sum_k x[n][k]*W1[j][128+k]
// Block: 64 nodes x 256 outputs, 256 threads, 8x8 register microtile each.
// x tile in smem (32 KB); weights streamed from global (L1-resident, 128 KB).
// ---------------------------------------------------------------------------
__global__ void __launch_bounds__(256) node_gemm_kernel(const float* __restrict__ x,
                                                        int n_nodes) {
    __shared__ float xs[NT * D];   // 32 KB

    int tid = threadIdx.x;
    int n0  = blockIdx.x * NT;

    for (int t = tid; t < NT * (D / 4); t += 256) {
        int n = t >> 5;          // node within tile
        int q = t & 31;          // float4 index within row
        float4 val = make_float4(0.f, 0.f, 0.f, 0.f);
        if (n0 + n < n_nodes)
            val = reinterpret_cast<const float4*>(x)[(size_t)(n0 + n) * (D / 4) + q];
        *reinterpret_cast<float4*>(&xs[n * D + q * 4]) = val;
    }
    __syncthreads();

    int jg = tid & 31;       // lanes cover all 256 outputs (8 each)
    int ng = tid >> 5;       // warp id: 8 nodes each
    int jbase = jg * 8;
    int nb    = ng * 8;

    float acc[8][8];
    #pragma unroll
    for (int i = 0; i < 8; i++)
        #pragma unroll
        for (int j = 0; j < 8; j++)
            acc[i][j] = 0.f;

    const float4* Wt4 = reinterpret_cast<const float4*>(g_Wt);

    #pragma unroll 4
    for (int kq = 0; kq < D / 2; kq++) {
        int k0 = kq * 2;
        float4 wa0 = Wt4[(k0 * 256 + jbase) >> 2];
        float4 wa1 = Wt4[(k0 * 256 + jbase + 4) >> 2];
        float4 wb0 = Wt4[((k0 + 1) * 256 + jbase) >> 2];
        float4 wb1 = Wt4[((k0 + 1) * 256 + jbase + 4) >> 2];
        float wa[8] = {wa0.x, wa0.y, wa0.z, wa0.w, wa1.x, wa1.y, wa1.z, wa1.w};
        float wb[8] = {wb0.x, wb0.y, wb0.z, wb0.w, wb1.x, wb1.y, wb1.z, wb1.w};
        #pragma unroll
        for (int i = 0; i < 8; i++) {
            float2 xv = *reinterpret_cast<const float2*>(&xs[(nb + i) * D + k0]);
            #pragma unroll
            for (int j = 0; j < 8; j++)
                acc[i][j] += xv.x * wa[j] + xv.y * wb[j];
        }
    }

    float* dst = (jg < 16) ? g_u : g_v;
    int jo = (jg < 16) ? jbase : (jbase - 128);
    #pragma unroll
    for (int i = 0; i < 8; i++) {
        int n = n0 + nb + i;
        if (n < n_nodes) {
            float4 o0 = make_float4(acc[i][0], acc[i][1], acc[i][2], acc[i][3]);
            float4 o1 = make_float4(acc[i][4], acc[i][5], acc[i][6], acc[i][7]);
            float4* p = reinterpret_cast<float4*>(dst + (size_t)n * D + jo);
            p[0] = o0;
            p[1] = o1;
        }
    }
}

// ---------------------------------------------------------------------------
// Edge phase: warp per edge. Lane l handles features [4l, 4l+4).
// out[e] = sum_j relu(u[s][j] + v[d][j] + b1[j]) * w2[j] + b2
// Index buffer interpreted per g_idx_is64 (set by sniff kernel).
// ---------------------------------------------------------------------------
__global__ void __launch_bounds__(256) edge_kernel(const int* __restrict__ idx32,
                                                   const float* __restrict__ b1,
                                                   const float* __restrict__ W2,
                                                   const float* __restrict__ b2,
                                                   float* __restrict__ out,
                                                   int E) {
    int lane   = threadIdx.x & 31;
    int warp   = (int)((blockIdx.x * blockDim.x + threadIdx.x) >> 5);
    int nwarps = (int)((gridDim.x * blockDim.x) >> 5);

    int is64 = g_idx_is64;
    // int32 layout:  src[e] = idx32[e],       dst[e] = idx32[E + e]
    // int64 layout:  src[e] = idx32[2e],      dst[e] = idx32[2E + 2e]   (low words)
    int mul  = is64 ? 2 : 1;
    int dofs = is64 ? 2 * E : E;

    float4 b1v = reinterpret_cast<const float4*>(b1)[lane];
    float4 w2v = reinterpret_cast<const float4*>(W2)[lane];
    float  b2s = __ldg(b2);

    int e = warp;
    for (; e + nwarps < E; e += 2 * nwarps) {
        int e2 = e + nwarps;
        int s1 = __ldg(&idx32[e * mul]);
        int d1 = __ldg(&idx32[dofs + e * mul]);
        int s2 = __ldg(&idx32[e2 * mul]);
        int d2 = __ldg(&idx32[dofs + e2 * mul]);

        float4 u1 = reinterpret_cast<const float4*>(g_u + (size_t)s1 * D)[lane];
        float4 v1 = reinterpret_cast<const float4*>(g_v + (size_t)d1 * D)[lane];
        float4 u2 = reinterpret_cast<const float4*>(g_u + (size_t)s2 * D)[lane];
        float4 v2 = reinterpret_cast<const float4*>(g_v + (size_t)d2 * D)[lane];

        float r1 = fmaxf(u1.x + v1.x + b1v.x, 0.f) * w2v.x
                 + fmaxf(u1.y + v1.y + b1v.y, 0.f) * w2v.y
                 + fmaxf(u1.z + v1.z + b1v.z, 0.f) * w2v.z
                 + fmaxf(u1.w + v1.w + b1v.w, 0.f) * w2v.w;
        float r2 = fmaxf(u2.x + v2.x + b1v.x, 0.f) * w2v.x
                 + fmaxf(u2.y + v2.y + b1v.y, 0.f) * w2v.y
                 + fmaxf(u2.z + v2.z + b1v.z, 0.f) * w2v.z
                 + fmaxf(u2.w + v2.w + b1v.w, 0.f) * w2v.w;

        #pragma unroll
        for (int off = 16; off; off >>= 1) {
            r1 += __shfl_xor_sync(0xffffffffu, r1, off);
            r2 += __shfl_xor_sync(0xffffffffu, r2, off);
        }
        if (lane == 0) {
            out[e]  = r1 + b2s;
            out[e2] = r2 + b2s;
        }
    }
    for (; e < E; e += nwarps) {
        int s = __ldg(&idx32[e * mul]);
        int d = __ldg(&idx32[dofs + e * mul]);
        float4 uu = reinterpret_cast<const float4*>(g_u + (size_t)s * D)[lane];
        float4 vv = reinterpret_cast<const float4*>(g_v + (size_t)d * D)[lane];
        float r = fmaxf(uu.x + vv.x + b1v.x, 0.f) * w2v.x
                + fmaxf(uu.y + vv.y + b1v.y, 0.f) * w2v.y
                + fmaxf(uu.z + vv.z + b1v.z, 0.f) * w2v.z
                + fmaxf(uu.w + vv.w + b1v.w, 0.f) * w2v.w;
        #pragma unroll
        for (int off = 16; off; off >>= 1)
            r += __shfl_xor_sync(0xffffffffu, r, off);
        if (lane == 0) out[e] = r + b2s;
    }
}

// ---------------------------------------------------------------------------
// Inputs (metadata order): x [100000,128] f32, edge_index [2,E] (int32 or
// int64 low-word layout — sniffed at runtime), W1 [128,256] f32, b1 [128] f32,
// W2 [1,128] f32, b2 [1] f32. Output: [E] f32.
// ---------------------------------------------------------------------------
extern "C" void kernel_launch(void* const* d_in, const int* in_sizes, int n_in,
                              void* d_out, int out_size) {
    const float* x    = (const float*)d_in[0];
    const int*   ei32 = (const int*)d_in[1];
    const float* W1   = (const float*)d_in[2];
    const float* b1   = (const float*)d_in[3];
    const float* W2   = (const float*)d_in[4];
    const float* b2   = (const float*)d_in[5];
    float* out = (float*)d_out;

    int n_nodes = in_sizes[0] / D;
    int E       = in_sizes[1] / 2;   // element count of edge_index is 2*E regardless of dtype

    // n_words for the sniffer: at least 2*E int32 words exist (int32 case);
    // pass 2*E to stay in-bounds for both interpretations.
    sniff_idx_kernel<<<1, 1>>>(ei32, 2 * E);
    transpose_W_kernel<<<(D * 2 * D + 255) / 256, 256>>>(W1);
    node_gemm_kernel<<<(n_nodes + NT - 1) / NT, 256>>>(x, n_nodes);
    edge_kernel<<<2048, 256>>>(ei32, b1, W2, b2, out, E);
}

// round 6
// speedup vs baseline: 1.9782x; 1.9782x over previous
#include <cuda_runtime.h>
#include <cuda_fp16.h>
#include <cstdint>

#define D 128
#define MAX_NODES 100000

// ---------------------------------------------------------------------------
// Scratch (__device__ globals; no allocation allowed)
// ---------------------------------------------------------------------------
__device__ float g_u[(size_t)MAX_NODES * D];   // u[n] = A x[n] + b1  (b1 folded)
__device__ float g_v[(size_t)MAX_NODES * D];   // v[n] = B x[n]
__device__ int   g_idx_is64;                   // edge_index dtype flag
// W fragments in exact mma.sync per-lane order:
// index ((ks*32 + ntile)*32 + lane) -> uint4 {b0_hi, b1_hi, b0_lo, b1_lo}
__device__ uint4 g_Wfrag[8 * 32 * 32];         // 128 KB

// ---------------------------------------------------------------------------
// Helpers
// ---------------------------------------------------------------------------
__device__ __forceinline__ uint32_t pack_hi_lo(float a, float b, uint32_t& lo_out) {
    __half ha = __float2half_rn(a), hb = __float2half_rn(b);
    float la = a - __half2float(ha), lb = b - __half2float(hb);
    __half2 H = __halves2half2(ha, hb);
    __half2 L = __floats2half2_rn(la, lb);
    lo_out = *reinterpret_cast<uint32_t*>(&L);
    return *reinterpret_cast<uint32_t*>(&H);
}

__device__ __forceinline__ void mma16816(float* c, const uint32_t* a,
                                         uint32_t b0, uint32_t b1) {
    asm volatile(
        "mma.sync.aligned.m16n8k16.row.col.f32.f16.f16.f32 "
        "{%0,%1,%2,%3}, {%4,%5,%6,%7}, {%8,%9}, {%0,%1,%2,%3};"
        : "+f"(c[0]), "+f"(c[1]), "+f"(c[2]), "+f"(c[3])
        : "r"(a[0]), "r"(a[1]), "r"(a[2]), "r"(a[3]), "r"(b0), "r"(b1));
}

// ---------------------------------------------------------------------------
// Index dtype sniffer: int64 little-endian with values < 2^31 -> all odd
// 32-bit words are zero. One warp, ballot.
// ---------------------------------------------------------------------------
__global__ void sniff_idx_kernel(const int* __restrict__ idx32) {
    int lane = threadIdx.x & 31;
    int nz = (idx32[2 * lane + 1] != 0) ? 1 : 0;
    unsigned m = __ballot_sync(0xffffffffu, nz);
    if (lane == 0) g_idx_is64 = (m == 0);
}

// ---------------------------------------------------------------------------
// Weight prep: build B fragments (hi/lo fp16) in mma.sync lane order.
// Logical B[k][n], k in [0,128), n in [0,256):
//   n <  128 : B[k][n] = W1[n][k]          (u outputs)
//   n >= 128 : B[k][n] = W1[n-128][128+k]  (v outputs)
// Fragment (m16n8k16, col-major B): lane: t=lane&3, g=lane>>2;
//   b0 = {B[ks*16+2t][n], B[ks*16+2t+1][n]}, b1 = {.. +8 ..}, n = ntile*8+g.
// ---------------------------------------------------------------------------
__global__ void prep_w_kernel(const float* __restrict__ W1) {
    int i = blockIdx.x * blockDim.x + threadIdx.x;   // 0..8191
    if (i >= 8 * 32 * 32) return;
    int lane = i & 31;
    int nt   = (i >> 5) & 31;
    int ks   = i >> 10;
    int t = lane & 3, g = lane >> 2;
    int n = nt * 8 + g;
    int k0 = ks * 16 + 2 * t;

    int j    = n & 127;
    int koff = (n >> 7) << 7;   // 0 for u, 128 for v
    float w0 = W1[j * 256 + koff + k0];
    float w1 = W1[j * 256 + koff + k0 + 1];
    float w2 = W1[j * 256 + koff + k0 + 8];
    float w3 = W1[j * 256 + koff + k0 + 9];

    uint32_t l0, l1;
    uint32_t h0 = pack_hi_lo(w0, w1, l0);
    uint32_t h1 = pack_hi_lo(w2, w3, l1);
    g_Wfrag[i] = make_uint4(h0, h1, l0, l1);
}

// ---------------------------------------------------------------------------
// Node GEMM via mma.sync fp16 split precision (3 products):
//   D = Ah*Bh + Al*Bh + Ah*Bl   (Al*Bl ~ 2^-24, dropped)
// CTA: 64 nodes x 256 outputs; 8 warps as 2(M) x 4(N); warp tile 32x64.
// x tile (64x128 fp32) staged once in smem; A fragments via LDS + cvt.
// b1 folded into u outputs.
// ---------------------------------------------------------------------------
#define XS_STRIDE 136

__global__ void __launch_bounds__(256, 1) node_gemm_mma(const float* __restrict__ x,
                                                        const float* __restrict__ b1,
                                                        int n_nodes) {
    __shared__ float xs[64 * XS_STRIDE];   // 34.8 KB

    int tid = threadIdx.x;
    int n0  = blockIdx.x * 64;

    // Stage x tile: 64 rows x 32 float4.
    const float4* x4 = reinterpret_cast<const float4*>(x);
    #pragma unroll
    for (int rep = 0; rep < 8; rep++) {
        int tt = tid + rep * 256;      // 0..2047
        int row = tt >> 5, q = tt & 31;
        float4 v = make_float4(0.f, 0.f, 0.f, 0.f);
        if (n0 + row < n_nodes) v = x4[(size_t)(n0 + row) * 32 + q];
        *reinterpret_cast<float4*>(&xs[row * XS_STRIDE + q * 4]) = v;
    }
    __syncthreads();

    int lane = tid & 31, wid = tid >> 5;
    int wM = wid >> 2;        // 0..1
    int wN = wid & 3;         // 0..3
    int t = lane & 3, g = lane >> 2;

    float acc[2][8][4];
    #pragma unroll
    for (int mt = 0; mt < 2; mt++)
        #pragma unroll
        for (int j = 0; j < 8; j++)
            #pragma unroll
            for (int q = 0; q < 4; q++) acc[mt][j][q] = 0.f;

    #pragma unroll 2
    for (int ks = 0; ks < 8; ks++) {
        int k0 = ks * 16;
        uint32_t ah[2][4], al[2][4];
        #pragma unroll
        for (int mt = 0; mt < 2; mt++) {
            int r = wM * 32 + mt * 16 + g;
            float2 r0 = *reinterpret_cast<const float2*>(&xs[r * XS_STRIDE + k0 + 2 * t]);
            float2 r1 = *reinterpret_cast<const float2*>(&xs[r * XS_STRIDE + k0 + 8 + 2 * t]);
            float2 r2 = *reinterpret_cast<const float2*>(&xs[(r + 8) * XS_STRIDE + k0 + 2 * t]);
            float2 r3 = *reinterpret_cast<const float2*>(&xs[(r + 8) * XS_STRIDE + k0 + 8 + 2 * t]);
            ah[mt][0] = pack_hi_lo(r0.x, r0.y, al[mt][0]);   // row g,   k 2t..
            ah[mt][1] = pack_hi_lo(r2.x, r2.y, al[mt][1]);   // row g+8, k 2t..
            ah[mt][2] = pack_hi_lo(r1.x, r1.y, al[mt][2]);   // row g,   k 2t+8..
            ah[mt][3] = pack_hi_lo(r3.x, r3.y, al[mt][3]);   // row g+8, k 2t+8..
        }
        #pragma unroll
        for (int j = 0; j < 8; j++) {
            uint4 f = __ldg(&g_Wfrag[((ks * 32 + wN * 8 + j) << 5) + lane]);
            #pragma unroll
            for (int mt = 0; mt < 2; mt++) {
                mma16816(acc[mt][j], ah[mt], f.x, f.y);   // Ah*Bh
                mma16816(acc[mt][j], al[mt], f.x, f.y);   // Al*Bh
                mma16816(acc[mt][j], ah[mt], f.z, f.w);   // Ah*Bl
            }
        }
    }

    // Epilogue: cols wN*64 + j*8 + 2t (+1). wN<2 -> u (+ b1 fold), wN>=2 -> v.
    float* dstbase = (wN < 2) ? g_u : g_v;
    int colbase = (wN < 2) ? wN * 64 : (wN - 2) * 64;
    #pragma unroll
    for (int mt = 0; mt < 2; mt++) {
        int node0 = n0 + wM * 32 + mt * 16 + g;
        int node1 = node0 + 8;
        #pragma unroll
        for (int j = 0; j < 8; j++) {
            int col = colbase + j * 8 + 2 * t;
            float bb0 = 0.f, bb1 = 0.f;
            if (wN < 2) { float2 bv = *reinterpret_cast<const float2*>(&b1[col]);
                          bb0 = bv.x; bb1 = bv.y; }
            if (node0 < n_nodes)
                *reinterpret_cast<float2*>(&dstbase[(size_t)node0 * D + col]) =
                    make_float2(acc[mt][j][0] + bb0, acc[mt][j][1] + bb1);
            if (node1 < n_nodes)
                *reinterpret_cast<float2*>(&dstbase[(size_t)node1 * D + col]) =
                    make_float2(acc[mt][j][2] + bb0, acc[mt][j][3] + bb1);
        }
    }
}

// ---------------------------------------------------------------------------
// Edge phase: warp per 4 edges (8 gather chains in flight).
// out[e] = sum_j relu(u'[s][j] + v[d][j]) * w2[j] + b2     (b1 already in u')
// ---------------------------------------------------------------------------
__global__ void __launch_bounds__(256) edge_kernel(const int* __restrict__ idx32,
                                                   const float* __restrict__ W2,
                                                   const float* __restrict__ b2,
                                                   float* __restrict__ out,
                                                   int E) {
    int lane   = threadIdx.x & 31;
    int warp   = (int)((blockIdx.x * blockDim.x + threadIdx.x) >> 5);
    int nwarps = (int)((gridDim.x * blockDim.x) >> 5);

    int is64 = g_idx_is64;
    int mul  = is64 ? 2 : 1;
    int dofs = is64 ? 2 * E : E;

    float4 w2v = reinterpret_cast<const float4*>(W2)[lane];
    float  b2s = __ldg(b2);

    int G = E >> 2;
    for (int gi = warp; gi < G; gi += nwarps) {
        int e0 = gi << 2;
        int s0 = __ldg(&idx32[(e0 + 0) * mul]);
        int s1 = __ldg(&idx32[(e0 + 1) * mul]);
        int s2 = __ldg(&idx32[(e0 + 2) * mul]);
        int s3 = __ldg(&idx32[(e0 + 3) * mul]);
        int d0 = __ldg(&idx32[dofs + (e0 + 0) * mul]);
        int d1 = __ldg(&idx32[dofs + (e0 + 1) * mul]);
        int d2 = __ldg(&idx32[dofs + (e0 + 2) * mul]);
        int d3 = __ldg(&idx32[dofs + (e0 + 3) * mul]);

        float4 u0 = reinterpret_cast<const float4*>(g_u + (size_t)s0 * D)[lane];
        float4 u1 = reinterpret_cast<const float4*>(g_u + (size_t)s1 * D)[lane];
        float4 u2 = reinterpret_cast<const float4*>(g_u + (size_t)s2 * D)[lane];
        float4 u3 = reinterpret_cast<const float4*>(g_u + (size_t)s3 * D)[lane];
        float4 v0 = reinterpret_cast<const float4*>(g_v + (size_t)d0 * D)[lane];
        float4 v1 = reinterpret_cast<const float4*>(g_v + (size_t)d1 * D)[lane];
        float4 v2 = reinterpret_cast<const float4*>(g_v + (size_t)d2 * D)[lane];
        float4 v3 = reinterpret_cast<const float4*>(g_v + (size_t)d3 * D)[lane];

        float r0 = fmaxf(u0.x + v0.x, 0.f) * w2v.x + fmaxf(u0.y + v0.y, 0.f) * w2v.y
                 + fmaxf(u0.z + v0.z, 0.f) * w2v.z + fmaxf(u0.w + v0.w, 0.f) * w2v.w;
        float r1 = fmaxf(u1.x + v1.x, 0.f) * w2v.x + fmaxf(u1.y + v1.y, 0.f) * w2v.y
                 + fmaxf(u1.z + v1.z, 0.f) * w2v.z + fmaxf(u1.w + v1.w, 0.f) * w2v.w;
        float r2 = fmaxf(u2.x + v2.x, 0.f) * w2v.x + fmaxf(u2.y + v2.y, 0.f) * w2v.y
                 + fmaxf(u2.z + v2.z, 0.f) * w2v.z + fmaxf(u2.w + v2.w, 0.f) * w2v.w;
        float r3 = fmaxf(u3.x + v3.x, 0.f) * w2v.x + fmaxf(u3.y + v3.y, 0.f) * w2v.y
                 + fmaxf(u3.z + v3.z, 0.f) * w2v.z + fmaxf(u3.w + v3.w, 0.f) * w2v.w;

        #pragma unroll
        for (int off = 16; off; off >>= 1) {
            r0 += __shfl_xor_sync(0xffffffffu, r0, off);
            r1 += __shfl_xor_sync(0xffffffffu, r1, off);
            r2 += __shfl_xor_sync(0xffffffffu, r2, off);
            r3 += __shfl_xor_sync(0xffffffffu, r3, off);
        }
        if (lane == 0)
            reinterpret_cast<float4*>(out + e0)[0] =
                make_float4(r0 + b2s, r1 + b2s, r2 + b2s, r3 + b2s);
    }

    int e = (E & ~3) + warp;
    if (e < E) {
        int s = __ldg(&idx32[e * mul]);
        int d = __ldg(&idx32[dofs + e * mul]);
        float4 uu = reinterpret_cast<const float4*>(g_u + (size_t)s * D)[lane];
        float4 vv = reinterpret_cast<const float4*>(g_v + (size_t)d * D)[lane];
        float r = fmaxf(uu.x + vv.x, 0.f) * w2v.x + fmaxf(uu.y + vv.y, 0.f) * w2v.y
                + fmaxf(uu.z + vv.z, 0.f) * w2v.z + fmaxf(uu.w + vv.w, 0.f) * w2v.w;
        #pragma unroll
        for (int off = 16; off; off >>= 1)
            r += __shfl_xor_sync(0xffffffffu, r, off);
        if (lane == 0) out[e] = r + b2s;
    }
}

// ---------------------------------------------------------------------------
// Inputs: x [100000,128] f32, edge_index [2,E] (int32/int64 sniffed),
// W1 [128,256] f32, b1 [128] f32, W2 [1,128] f32, b2 [1] f32. Output: [E] f32.
// ---------------------------------------------------------------------------
extern "C" void kernel_launch(void* const* d_in, const int* in_sizes, int n_in,
                              void* d_out, int out_size) {
    const float* x    = (const float*)d_in[0];
    const int*   ei32 = (const int*)d_in[1];
    const float* W1   = (const float*)d_in[2];
    const float* b1   = (const float*)d_in[3];
    const float* W2   = (const float*)d_in[4];
    const float* b2   = (const float*)d_in[5];
    float* out = (float*)d_out;

    int n_nodes = in_sizes[0] / D;
    int E       = in_sizes[1] / 2;

    sniff_idx_kernel<<<1, 32>>>(ei32);
    prep_w_kernel<<<32, 256>>>(W1);
    node_gemm_mma<<<(n_nodes + 63) / 64, 256>>>(x, b1, n_nodes);
    edge_kernel<<<2048, 256>>>(ei32, W2, b2, out, E);
}

// round 7
// speedup vs baseline: 2.5776x; 1.3030x over previous
#include <cuda_runtime.h>
#include <cuda_fp16.h>
#include <cstdint>

#define D 128
#define MAX_NODES 100000

// ---------------------------------------------------------------------------
// Scratch (__device__ globals; no allocation allowed)
// ---------------------------------------------------------------------------
__device__ __half g_u[(size_t)MAX_NODES * D];  // u[n] = A x[n] + b1 (fp16)
__device__ __half g_v[(size_t)MAX_NODES * D];  // v[n] = B x[n]     (fp16)
__device__ int    g_idx_is64;                  // edge_index dtype flag
// W fragments in exact mma.sync per-lane order:
// index ((ks*32 + ntile)*32 + lane) -> uint4 {b0_hi, b1_hi, b0_lo, b1_lo}
__device__ uint4  g_Wfrag[8 * 32 * 32];        // 128 KB

// ---------------------------------------------------------------------------
// Helpers
// ---------------------------------------------------------------------------
__device__ __forceinline__ uint32_t smem_u32(const void* p) {
    uint32_t a;
    asm("{ .reg .u64 t; cvta.to.shared.u64 t, %1; cvt.u32.u64 %0, t; }" : "=r"(a) : "l"(p));
    return a;
}

__device__ __forceinline__ uint32_t pack_hi_lo(float a, float b, uint32_t& lo_out) {
    __half ha = __float2half_rn(a), hb = __float2half_rn(b);
    float la = a - __half2float(ha), lb = b - __half2float(hb);
    __half2 H = __halves2half2(ha, hb);
    __half2 L = __floats2half2_rn(la, lb);
    lo_out = *reinterpret_cast<uint32_t*>(&L);
    return *reinterpret_cast<uint32_t*>(&H);
}

__device__ __forceinline__ void mma16816(float* c, const uint32_t* a,
                                         uint32_t b0, uint32_t b1) {
    asm volatile(
        "mma.sync.aligned.m16n8k16.row.col.f32.f16.f16.f32 "
        "{%0,%1,%2,%3}, {%4,%5,%6,%7}, {%8,%9}, {%0,%1,%2,%3};"
        : "+f"(c[0]), "+f"(c[1]), "+f"(c[2]), "+f"(c[3])
        : "r"(a[0]), "r"(a[1]), "r"(a[2]), "r"(a[3]), "r"(b0), "r"(b1));
}

#define LDMATRIX_X4(r, addr) \
    asm volatile("ldmatrix.sync.aligned.m8n8.x4.shared.b16 {%0,%1,%2,%3}, [%4];" \
                 : "=r"((r)[0]), "=r"((r)[1]), "=r"((r)[2]), "=r"((r)[3]) \
                 : "r"(addr))

// ---------------------------------------------------------------------------
// Index dtype sniffer: int64 little-endian with values < 2^31 -> all odd
// 32-bit words are zero. One warp, ballot.
// ---------------------------------------------------------------------------
__global__ void sniff_idx_kernel(const int* __restrict__ idx32) {
    int lane = threadIdx.x & 31;
    int nz = (idx32[2 * lane + 1] != 0) ? 1 : 0;
    unsigned m = __ballot_sync(0xffffffffu, nz);
    if (lane == 0) g_idx_is64 = (m == 0);
}

// ---------------------------------------------------------------------------
// Weight prep: B fragments (hi/lo fp16) in mma.sync lane order.
// Logical B[k][n]: n<128 -> W1[n][k] (u), n>=128 -> W1[n-128][128+k] (v).
// Lane: t=lane&3, g=lane>>2; b0={B[ks*16+2t][n],B[..+1][n]}, b1 same at k+8,
// n = ntile*8+g.
// ---------------------------------------------------------------------------
__global__ void prep_w_kernel(const float* __restrict__ W1) {
    int i = blockIdx.x * blockDim.x + threadIdx.x;   // 0..8191
    if (i >= 8 * 32 * 32) return;
    int lane = i & 31;
    int nt   = (i >> 5) & 31;
    int ks   = i >> 10;
    int t = lane & 3, g = lane >> 2;
    int n = nt * 8 + g;
    int k0 = ks * 16 + 2 * t;

    int j    = n & 127;
    int koff = (n >> 7) << 7;   // 0 for u, 128 for v
    float w0 = W1[j * 256 + koff + k0];
    float w1 = W1[j * 256 + koff + k0 + 1];
    float w2 = W1[j * 256 + koff + k0 + 8];
    float w3 = W1[j * 256 + koff + k0 + 9];

    uint32_t l0, l1;
    uint32_t h0 = pack_hi_lo(w0, w1, l0);
    uint32_t h1 = pack_hi_lo(w2, w3, l1);
    g_Wfrag[i] = make_uint4(h0, h1, l0, l1);
}

// ---------------------------------------------------------------------------
// Node GEMM via mma.sync fp16 split precision: D = Ah*Bh + Al*Bh + Ah*Bl.
// CTA: 64 nodes x 256 outputs; 8 warps 2(M)x4(N); warp tile 32x64.
// x tile converted ONCE to fp16 hi/lo in smem (272 B row stride ->
// conflict-free ldmatrix); A fragments via ldmatrix.x4.
// b1 folded into u outputs; outputs stored as fp16.
// ---------------------------------------------------------------------------
#define XH_STRIDE 136   // halves per row (272 B)

__global__ void __launch_bounds__(256, 1) node_gemm_mma(const float* __restrict__ x,
                                                        const float* __restrict__ b1,
                                                        int n_nodes) {
    __shared__ __align__(16) __half xh[64 * XH_STRIDE];  // 17408 B
    __shared__ __align__(16) __half xl[64 * XH_STRIDE];  // 17408 B

    int tid = threadIdx.x;
    int n0  = blockIdx.x * 64;

    // Stage x tile as fp16 hi/lo (single conversion per element per CTA).
    const float4* x4 = reinterpret_cast<const float4*>(x);
    #pragma unroll
    for (int rep = 0; rep < 8; rep++) {
        int tt = tid + rep * 256;      // 0..2047
        int row = tt >> 5, q = tt & 31;
        float4 v = make_float4(0.f, 0.f, 0.f, 0.f);
        if (n0 + row < n_nodes) v = x4[(size_t)(n0 + row) * 32 + q];
        uint32_t l01, l23;
        uint32_t h01 = pack_hi_lo(v.x, v.y, l01);
        uint32_t h23 = pack_hi_lo(v.z, v.w, l23);
        int hofs = row * XH_STRIDE + q * 4;     // halves
        *reinterpret_cast<uint2*>(&xh[hofs]) = make_uint2(h01, h23);
        *reinterpret_cast<uint2*>(&xl[hofs]) = make_uint2(l01, l23);
    }
    __syncthreads();

    int lane = tid & 31, wid = tid >> 5;
    int wM = wid >> 2;        // 0..1
    int wN = wid & 3;         // 0..3
    int t = lane & 3, g = lane >> 2;

    // ldmatrix lane addressing: lanes 0-15 -> rows (L&15), k-block 0;
    // lanes 16-31 -> rows (L&15), k-block 1 (+8 halves = +16 B).
    int lrow = wM * 32 + (lane & 15);
    int lkb  = lane >> 4;
    uint32_t ph0 = smem_u32(xh) + (uint32_t)(lrow * XH_STRIDE + lkb * 8) * 2;
    uint32_t pl0 = smem_u32(xl) + (uint32_t)(lrow * XH_STRIDE + lkb * 8) * 2;

    float acc[2][8][4];
    #pragma unroll
    for (int mt = 0; mt < 2; mt++)
        #pragma unroll
        for (int j = 0; j < 8; j++)
            #pragma unroll
            for (int q = 0; q < 4; q++) acc[mt][j][q] = 0.f;

    #pragma unroll
    for (int ks = 0; ks < 8; ks++) {
        uint32_t ah[2][4], al[2][4];
        uint32_t ko = ks * 32;                       // 16 halves = 32 B per ks
        LDMATRIX_X4(ah[0], ph0 + ko);
        LDMATRIX_X4(ah[1], ph0 + ko + 16 * XH_STRIDE * 2);
        LDMATRIX_X4(al[0], pl0 + ko);
        LDMATRIX_X4(al[1], pl0 + ko + 16 * XH_STRIDE * 2);
        #pragma unroll
        for (int j = 0; j < 8; j++) {
            uint4 f = __ldg(&g_Wfrag[((ks * 32 + wN * 8 + j) << 5) + lane]);
            #pragma unroll
            for (int mt = 0; mt < 2; mt++) {
                mma16816(acc[mt][j], ah[mt], f.x, f.y);   // Ah*Bh
                mma16816(acc[mt][j], al[mt], f.x, f.y);   // Al*Bh
                mma16816(acc[mt][j], ah[mt], f.z, f.w);   // Ah*Bl
            }
        }
    }

    // Epilogue: cols wN*64 + j*8 + 2t. wN<2 -> u (+ b1 fold), wN>=2 -> v.
    // Stored as half2.
    __half* dstbase = (wN < 2) ? g_u : g_v;
    int colbase = (wN < 2) ? wN * 64 : (wN - 2) * 64;
    #pragma unroll
    for (int mt = 0; mt < 2; mt++) {
        int node0 = n0 + wM * 32 + mt * 16 + g;
        int node1 = node0 + 8;
        #pragma unroll
        for (int j = 0; j < 8; j++) {
            int col = colbase + j * 8 + 2 * t;
            float bb0 = 0.f, bb1 = 0.f;
            if (wN < 2) { float2 bv = *reinterpret_cast<const float2*>(&b1[col]);
                          bb0 = bv.x; bb1 = bv.y; }
            if (node0 < n_nodes)
                *reinterpret_cast<__half2*>(&dstbase[(size_t)node0 * D + col]) =
                    __floats2half2_rn(acc[mt][j][0] + bb0, acc[mt][j][1] + bb1);
            if (node1 < n_nodes)
                *reinterpret_cast<__half2*>(&dstbase[(size_t)node1 * D + col]) =
                    __floats2half2_rn(acc[mt][j][2] + bb0, acc[mt][j][3] + bb1);
        }
    }
}

// ---------------------------------------------------------------------------
// Edge phase: warp per 4 edges. Lane l handles features [4l, 4l+4) as fp16
// (uint2 gather = 8 B/lane, 256 B/row, 2 lines). fp32 math after convert.
// out[e] = sum_j relu(u'[s][j] + v[d][j]) * w2[j] + b2
// ---------------------------------------------------------------------------
__device__ __forceinline__ float edge_dot(uint2 ur, uint2 vr, float4 w2v) {
    float2 u0 = __half22float2(*reinterpret_cast<__half2*>(&ur.x));
    float2 u1 = __half22float2(*reinterpret_cast<__half2*>(&ur.y));
    float2 v0 = __half22float2(*reinterpret_cast<__half2*>(&vr.x));
    float2 v1 = __half22float2(*reinterpret_cast<__half2*>(&vr.y));
    return fmaxf(u0.x + v0.x, 0.f) * w2v.x + fmaxf(u0.y + v0.y, 0.f) * w2v.y
         + fmaxf(u1.x + v1.x, 0.f) * w2v.z + fmaxf(u1.y + v1.y, 0.f) * w2v.w;
}

__global__ void __launch_bounds__(256) edge_kernel(const int* __restrict__ idx32,
                                                   const float* __restrict__ W2,
                                                   const float* __restrict__ b2,
                                                   float* __restrict__ out,
                                                   int E) {
    int lane   = threadIdx.x & 31;
    int warp   = (int)((blockIdx.x * blockDim.x + threadIdx.x) >> 5);
    int nwarps = (int)((gridDim.x * blockDim.x) >> 5);

    int is64 = g_idx_is64;
    int mul  = is64 ? 2 : 1;
    int dofs = is64 ? 2 * E : E;

    float4 w2v = reinterpret_cast<const float4*>(W2)[lane];
    float  b2s = __ldg(b2);

    const uint2* U = reinterpret_cast<const uint2*>(g_u);  // 32 uint2 per row
    const uint2* V = reinterpret_cast<const uint2*>(g_v);

    int G = E >> 2;
    for (int gi = warp; gi < G; gi += nwarps) {
        int e0 = gi << 2;
        int s0 = __ldg(&idx32[(e0 + 0) * mul]);
        int s1 = __ldg(&idx32[(e0 + 1) * mul]);
        int s2 = __ldg(&idx32[(e0 + 2) * mul]);
        int s3 = __ldg(&idx32[(e0 + 3) * mul]);
        int d0 = __ldg(&idx32[dofs + (e0 + 0) * mul]);
        int d1 = __ldg(&idx32[dofs + (e0 + 1) * mul]);
        int d2 = __ldg(&idx32[dofs + (e0 + 2) * mul]);
        int d3 = __ldg(&idx32[dofs + (e0 + 3) * mul]);

        uint2 u0 = __ldg(&U[(size_t)s0 * 32 + lane]);
        uint2 u1 = __ldg(&U[(size_t)s1 * 32 + lane]);
        uint2 u2 = __ldg(&U[(size_t)s2 * 32 + lane]);
        uint2 u3 = __ldg(&U[(size_t)s3 * 32 + lane]);
        uint2 v0 = __ldg(&V[(size_t)d0 * 32 + lane]);
        uint2 v1 = __ldg(&V[(size_t)d1 * 32 + lane]);
        uint2 v2 = __ldg(&V[(size_t)d2 * 32 + lane]);
        uint2 v3 = __ldg(&V[(size_t)d3 * 32 + lane]);

        float r0 = edge_dot(u0, v0, w2v);
        float r1 = edge_dot(u1, v1, w2v);
        float r2 = edge_dot(u2, v2, w2v);
        float r3 = edge_dot(u3, v3, w2v);

        #pragma unroll
        for (int off = 16; off; off >>= 1) {
            r0 += __shfl_xor_sync(0xffffffffu, r0, off);
            r1 += __shfl_xor_sync(0xffffffffu, r1, off);
            r2 += __shfl_xor_sync(0xffffffffu, r2, off);
            r3 += __shfl_xor_sync(0xffffffffu, r3, off);
        }
        if (lane == 0)
            reinterpret_cast<float4*>(out + e0)[0] =
                make_float4(r0 + b2s, r1 + b2s, r2 + b2s, r3 + b2s);
    }

    int e = (E & ~3) + warp;
    if (e < E) {
        int s = __ldg(&idx32[e * mul]);
        int d = __ldg(&idx32[dofs + e * mul]);
        uint2 uu = __ldg(&U[(size_t)s * 32 + lane]);
        uint2 vv = __ldg(&V[(size_t)d * 32 + lane]);
        float r = edge_dot(uu, vv, w2v);
        #pragma unroll
        for (int off = 16; off; off >>= 1)
            r += __shfl_xor_sync(0xffffffffu, r, off);
        if (lane == 0) out[e] = r + b2s;
    }
}

// ---------------------------------------------------------------------------
// Inputs: x [100000,128] f32, edge_index [2,E] (int32/int64 sniffed),
// W1 [128,256] f32, b1 [128] f32, W2 [1,128] f32, b2 [1] f32. Output: [E] f32.
// ---------------------------------------------------------------------------
extern "C" void kernel_launch(void* const* d_in, const int* in_sizes, int n_in,
                              void* d_out, int out_size) {
    const float* x    = (const float*)d_in[0];
    const int*   ei32 = (const int*)d_in[1];
    const float* W1   = (const float*)d_in[2];
    const float* b1   = (const float*)d_in[3];
    const float* W2   = (const float*)d_in[4];
    const float* b2   = (const float*)d_in[5];
    float* out = (float*)d_out;

    int n_nodes = in_sizes[0] / D;
    int E       = in_sizes[1] / 2;

    sniff_idx_kernel<<<1, 32>>>(ei32);
    prep_w_kernel<<<32, 256>>>(W1);
    node_gemm_mma<<<(n_nodes + 63) / 64, 256>>>(x, b1, n_nodes);
    edge_kernel<<<2048, 256>>>(ei32, W2, b2, out, E);
}

// round 10
// speedup vs baseline: 2.7887x; 1.0819x over previous
#include <cuda_runtime.h>
#include <cuda_fp16.h>
#include <cstdint>

#define D 128
#define MAX_NODES 100000

// ---------------------------------------------------------------------------
// Scratch (__device__ globals; no allocation allowed)
// ---------------------------------------------------------------------------
__device__ uint4  g_u4[(size_t)MAX_NODES * 16];   // u[n] = A x[n] + b1 (fp16, 128/row)
__device__ uint4  g_v4[(size_t)MAX_NODES * 16];   // v[n] = B x[n]     (fp16)
__device__ int    g_idx_is64;                     // edge_index dtype flag
// W fragments in exact mma.sync per-lane order:
// index ((ks*32 + ntile)*32 + lane) -> uint4 {b0_hi, b1_hi, b0_lo, b1_lo}
__device__ uint4  g_Wfrag[8 * 32 * 32];           // 128 KB

// ---------------------------------------------------------------------------
// Helpers
// ---------------------------------------------------------------------------
__device__ __forceinline__ uint32_t smem_u32(const void* p) {
    uint32_t a;
    asm("{ .reg .u64 t; cvta.to.shared.u64 t, %1; cvt.u32.u64 %0, t; }" : "=r"(a) : "l"(p));
    return a;
}

__device__ __forceinline__ uint32_t pack_hi_lo(float a, float b, uint32_t& lo_out) {
    __half ha = __float2half_rn(a), hb = __float2half_rn(b);
    float la = a - __half2float(ha), lb = b - __half2float(hb);
    __half2 H = __halves2half2(ha, hb);
    __half2 L = __floats2half2_rn(la, lb);
    lo_out = *reinterpret_cast<uint32_t*>(&L);
    return *reinterpret_cast<uint32_t*>(&H);
}

__device__ __forceinline__ void mma16816(float* c, const uint32_t* a,
                                         uint32_t b0, uint32_t b1) {
    asm volatile(
        "mma.sync.aligned.m16n8k16.row.col.f32.f16.f16.f32 "
        "{%0,%1,%2,%3}, {%4,%5,%6,%7}, {%8,%9}, {%0,%1,%2,%3};"
        : "+f"(c[0]), "+f"(c[1]), "+f"(c[2]), "+f"(c[3])
        : "r"(a[0]), "r"(a[1]), "r"(a[2]), "r"(a[3]), "r"(b0), "r"(b1));
}

#define LDMATRIX_X4(r, addr) \
    asm volatile("ldmatrix.sync.aligned.m8n8.x4.shared.b16 {%0,%1,%2,%3}, [%4];" \
                 : "=r"((r)[0]), "=r"((r)[1]), "=r"((r)[2]), "=r"((r)[3]) \
                 : "r"(addr))

// ---------------------------------------------------------------------------
// Index dtype sniffer: int64 little-endian with values < 2^31 -> all odd
// 32-bit words are zero. One warp, ballot.
// ---------------------------------------------------------------------------
__global__ void sniff_idx_kernel(const int* __restrict__ idx32) {
    int lane = threadIdx.x & 31;
    int nz = (idx32[2 * lane + 1] != 0) ? 1 : 0;
    unsigned m = __ballot_sync(0xffffffffu, nz);
    if (lane == 0) g_idx_is64 = (m == 0);
}

// ---------------------------------------------------------------------------
// Weight prep: B fragments (hi/lo fp16) in mma.sync lane order.
// Logical B[k][n]: n<128 -> W1[n][k] (u), n>=128 -> W1[n-128][128+k] (v).
// Lane: t=lane&3, g=lane>>2; b0={B[ks*16+2t][n],B[..+1][n]}, b1 same at k+8,
// n = ntile*8+g.
// ---------------------------------------------------------------------------
__global__ void prep_w_kernel(const float* __restrict__ W1) {
    int i = blockIdx.x * blockDim.x + threadIdx.x;   // 0..8191
    if (i >= 8 * 32 * 32) return;
    int lane = i & 31;
    int nt   = (i >> 5) & 31;
    int ks   = i >> 10;
    int t = lane & 3, g = lane >> 2;
    int n = nt * 8 + g;
    int k0 = ks * 16 + 2 * t;

    int j    = n & 127;
    int koff = (n >> 7) << 7;   // 0 for u, 128 for v
    float w0 = W1[j * 256 + koff + k0];
    float w1 = W1[j * 256 + koff + k0 + 1];
    float w2 = W1[j * 256 + koff + k0 + 8];
    float w3 = W1[j * 256 + koff + k0 + 9];

    uint32_t l0, l1;
    uint32_t h0 = pack_hi_lo(w0, w1, l0);
    uint32_t h1 = pack_hi_lo(w2, w3, l1);
    g_Wfrag[i] = make_uint4(h0, h1, l0, l1);
}

// ---------------------------------------------------------------------------
// Node GEMM via mma.sync fp16 split precision: D = Ah*Bh + Al*Bh + Ah*Bl.
// CTA: 128 nodes x 256 outputs; 8 warps as 2(M) x 4(N); warp tile 64x64
// (mt = 4 row-tiles of 16) -- doubles B-fragment reuse vs 32-row warps.
// x tile converted ONCE to fp16 hi/lo in dynamic smem (272 B row stride,
// conflict-free ldmatrix). b1 folded into u; outputs stored fp16.
// ---------------------------------------------------------------------------
#define XH_STRIDE 136                        // halves per row (272 B)
#define XTILE_BYTES (128 * XH_STRIDE * 2)    // 34816 B per buffer
#define GEMM_SMEM (2 * XTILE_BYTES)          // 69632 B

__global__ void __launch_bounds__(256, 1) node_gemm_mma(const float* __restrict__ x,
                                                        const float* __restrict__ b1,
                                                        int n_nodes) {
    extern __shared__ __align__(16) char dsm[];
    __half* xh = reinterpret_cast<__half*>(dsm);
    __half* xl = reinterpret_cast<__half*>(dsm + XTILE_BYTES);

    int tid = threadIdx.x;
    int n0  = blockIdx.x * 128;

    // Stage x tile as fp16 hi/lo: 128 rows x 32 float4 = 4096 loads.
    const float4* x4 = reinterpret_cast<const float4*>(x);
    #pragma unroll
    for (int rep = 0; rep < 16; rep++) {
        int tt = tid + rep * 256;      // 0..4095
        int row = tt >> 5, q = tt & 31;
        float4 v = make_float4(0.f, 0.f, 0.f, 0.f);
        if (n0 + row < n_nodes) v = x4[(size_t)(n0 + row) * 32 + q];
        uint32_t l01, l23;
        uint32_t h01 = pack_hi_lo(v.x, v.y, l01);
        uint32_t h23 = pack_hi_lo(v.z, v.w, l23);
        int hofs = row * XH_STRIDE + q * 4;     // halves
        *reinterpret_cast<uint2*>(&xh[hofs]) = make_uint2(h01, h23);
        *reinterpret_cast<uint2*>(&xl[hofs]) = make_uint2(l01, l23);
    }
    __syncthreads();

    int lane = tid & 31, wid = tid >> 5;
    int wM = wid >> 2;        // 0..1 : 64-row group
    int wN = wid & 3;         // 0..3 : 64-col group
    int t = lane & 3, g = lane >> 2;

    // ldmatrix lane addressing: lanes 0-15 -> rows (L&15), k-block 0;
    // lanes 16-31 -> same rows, k-block 1 (+8 halves = +16 B).
    int lrow = wM * 64 + (lane & 15);
    int lkb  = lane >> 4;
    uint32_t ph0 = smem_u32(xh) + (uint32_t)(lrow * XH_STRIDE + lkb * 8) * 2;
    uint32_t pl0 = smem_u32(xl) + (uint32_t)(lrow * XH_STRIDE + lkb * 8) * 2;

    float acc[4][8][4];
    #pragma unroll
    for (int mt = 0; mt < 4; mt++)
        #pragma unroll
        for (int j = 0; j < 8; j++)
            #pragma unroll
            for (int q = 0; q < 4; q++) acc[mt][j][q] = 0.f;

    #pragma unroll
    for (int ks = 0; ks < 8; ks++) {
        uint32_t ah[4][4], al[4][4];
        uint32_t ko = ks * 32;                       // 16 halves = 32 B per ks
        #pragma unroll
        for (int mt = 0; mt < 4; mt++) {
            uint32_t ro = ko + (uint32_t)(mt * 16 * XH_STRIDE * 2);
            LDMATRIX_X4(ah[mt], ph0 + ro);
            LDMATRIX_X4(al[mt], pl0 + ro);
        }
        #pragma unroll
        for (int j = 0; j < 8; j++) {
            uint4 f = __ldg(&g_Wfrag[((ks * 32 + wN * 8 + j) << 5) + lane]);
            #pragma unroll
            for (int mt = 0; mt < 4; mt++) {
                mma16816(acc[mt][j], ah[mt], f.x, f.y);   // Ah*Bh
                mma16816(acc[mt][j], al[mt], f.x, f.y);   // Al*Bh
                mma16816(acc[mt][j], ah[mt], f.z, f.w);   // Ah*Bl
            }
        }
    }

    // Epilogue: cols wN*64 + j*8 + 2t. wN<2 -> u (+ b1 fold), wN>=2 -> v.
    __half* dstbase = reinterpret_cast<__half*>((wN < 2) ? g_u4 : g_v4);
    int colbase = (wN < 2) ? wN * 64 : (wN - 2) * 64;
    #pragma unroll
    for (int mt = 0; mt < 4; mt++) {
        int node0 = n0 + wM * 64 + mt * 16 + g;
        int node1 = node0 + 8;
        #pragma unroll
        for (int j = 0; j < 8; j++) {
            int col = colbase + j * 8 + 2 * t;
            float bb0 = 0.f, bb1 = 0.f;
            if (wN < 2) { float2 bv = *reinterpret_cast<const float2*>(&b1[col]);
                          bb0 = bv.x; bb1 = bv.y; }
            if (node0 < n_nodes)
                *reinterpret_cast<__half2*>(&dstbase[(size_t)node0 * D + col]) =
                    __floats2half2_rn(acc[mt][j][0] + bb0, acc[mt][j][1] + bb1);
            if (node1 < n_nodes)
                *reinterpret_cast<__half2*>(&dstbase[(size_t)node1 * D + col]) =
                    __floats2half2_rn(acc[mt][j][2] + bb0, acc[mt][j][3] + bb1);
        }
    }
}

// ---------------------------------------------------------------------------
// Edge phase: 8 lanes per edge, 4 edges per warp iteration.
// Lane: sub = lane>>3 (edge), fl = lane&7 (features [fl*16, fl*16+16)).
// Packed fp16 add+relu, fp32 dot; 3-stage shuffle reduce within 8 lanes.
// out[e] = sum_j relu(u'[s][j] + v[d][j]) * w2[j] + b2   (b1 already in u')
// ---------------------------------------------------------------------------
__device__ __forceinline__ float dot16(uint4 uu, uint4 vv, const float* w2r) {
    const __half2* up = reinterpret_cast<const __half2*>(&uu);
    const __half2* vp = reinterpret_cast<const __half2*>(&vv);
    __half2 zero = __float2half2_rn(0.f);
    float r = 0.f;
    #pragma unroll
    for (int i = 0; i < 4; i++) {
        __half2 h = __hmax2(__hadd2(up[i], vp[i]), zero);
        float2 f = __half22float2(h);
        r = fmaf(f.x, w2r[2 * i], r);
        r = fmaf(f.y, w2r[2 * i + 1], r);
    }
    return r;
}

__global__ void __launch_bounds__(256) edge_kernel(const int* __restrict__ idx32,
                                                   const float* __restrict__ W2,
                                                   const float* __restrict__ b2,
                                                   float* __restrict__ out,
                                                   int E) {
    int lane   = threadIdx.x & 31;
    int sub    = lane >> 3;        // edge within group
    int fl     = lane & 7;         // feature-lane
    int warp   = (int)((blockIdx.x * blockDim.x + threadIdx.x) >> 5);
    int nwarps = (int)((gridDim.x * blockDim.x) >> 5);

    int is64 = g_idx_is64;
    int mul  = is64 ? 2 : 1;
    int dofs = is64 ? 2 * E : E;

    // w2 for this lane's 16 features.
    float w2r[16];
    #pragma unroll
    for (int q = 0; q < 4; q++) {
        float4 wv = reinterpret_cast<const float4*>(W2)[fl * 4 + q];
        w2r[4 * q + 0] = wv.x; w2r[4 * q + 1] = wv.y;
        w2r[4 * q + 2] = wv.z; w2r[4 * q + 3] = wv.w;
    }
    float b2s = __ldg(b2);

    int G = E >> 2;
    for (int gi = warp; gi < G; gi += nwarps) {
        int e = (gi << 2) + sub;
        int s = __ldg(&idx32[e * mul]);
        int d = __ldg(&idx32[dofs + e * mul]);

        const uint4* Ur = g_u4 + (size_t)s * 16 + fl * 2;
        const uint4* Vr = g_v4 + (size_t)d * 16 + fl * 2;
        uint4 u0 = __ldg(Ur), u1 = __ldg(Ur + 1);
        uint4 v0 = __ldg(Vr), v1 = __ldg(Vr + 1);

        float r = dot16(u0, v0, w2r) + dot16(u1, v1, w2r + 8);

        r += __shfl_xor_sync(0xffffffffu, r, 4);
        r += __shfl_xor_sync(0xffffffffu, r, 2);
        r += __shfl_xor_sync(0xffffffffu, r, 1);

        if (fl == 0) out[e] = r + b2s;   // 4 lanes -> coalesced 16 B
    }

    // tail (E % 4 edges), handled by warp 0
    int rem = E & 3;
    if (warp == 0 && sub < rem) {
        int e = (E & ~3) + sub;
        int s = __ldg(&idx32[e * mul]);
        int d = __ldg(&idx32[dofs + e * mul]);
        const uint4* Ur = g_u4 + (size_t)s * 16 + fl * 2;
        const uint4* Vr = g_v4 + (size_t)d * 16 + fl * 2;
        uint4 u0 = __ldg(Ur), u1 = __ldg(Ur + 1);
        uint4 v0 = __ldg(Vr), v1 = __ldg(Vr + 1);
        float r = dot16(u0, v0, w2r) + dot16(u1, v1, w2r + 8);
        r += __shfl_xor_sync(0xffffffffu, r, 4);
        r += __shfl_xor_sync(0xffffffffu, r, 2);
        r += __shfl_xor_sync(0xffffffffu, r, 1);
        if (fl == 0) out[e] = r + b2s;
    }
}

// ---------------------------------------------------------------------------
// Inputs: x [100000,128] f32, edge_index [2,E] (int32/int64 sniffed),
// W1 [128,256] f32, b1 [128] f32, W2 [1,128] f32, b2 [1] f32. Output: [E] f32.
// ---------------------------------------------------------------------------
extern "C" void kernel_launch(void* const* d_in, const int* in_sizes, int n_in,
                              void* d_out, int out_size) {
    const float* x    = (const float*)d_in[0];
    const int*   ei32 = (const int*)d_in[1];
    const float* W1   = (const float*)d_in[2];
    const float* b1   = (const float*)d_in[3];
    const float* W2   = (const float*)d_in[4];
    const float* b2   = (const float*)d_in[5];
    float* out = (float*)d_out;

    int n_nodes = in_sizes[0] / D;
    int E       = in_sizes[1] / 2;

    cudaFuncSetAttribute(node_gemm_mma, cudaFuncAttributeMaxDynamicSharedMemorySize,
                         GEMM_SMEM);

    sniff_idx_kernel<<<1, 32>>>(ei32);
    prep_w_kernel<<<32, 256>>>(W1);
    node_gemm_mma<<<(n_nodes + 127) / 128, 256, GEMM_SMEM>>>(x, b1, n_nodes);
    edge_kernel<<<2048, 256>>>(ei32, W2, b2, out, E);
}

// round 12
// speedup vs baseline: 3.6059x; 1.2930x over previous
#include <cuda_runtime.h>
#include <cuda_fp16.h>
#include <cstdint>

#define D 128
#define MAX_NODES 100000

// ---------------------------------------------------------------------------
// Scratch (__device__ globals; no allocation allowed)
// ---------------------------------------------------------------------------
__device__ uint4  g_u4[(size_t)MAX_NODES * 16];   // u[n] = A x[n] + b1 (fp16, 128/row)
__device__ uint4  g_v4[(size_t)MAX_NODES * 16];   // v[n] = B x[n]     (fp16)
__device__ int    g_idx_is64;                     // edge_index dtype flag
// W fragments in exact mma.sync per-lane order:
// index ((ks*32 + ntile)*32 + lane) -> uint4 {b0_hi, b1_hi, b0_lo, b1_lo}
__device__ uint4  g_Wfrag[8 * 32 * 32];           // 128 KB

// ---------------------------------------------------------------------------
// Helpers
// ---------------------------------------------------------------------------
__device__ __forceinline__ uint32_t smem_u32(const void* p) {
    uint32_t a;
    asm("{ .reg .u64 t; cvta.to.shared.u64 t, %1; cvt.u32.u64 %0, t; }" : "=r"(a) : "l"(p));
    return a;
}

__device__ __forceinline__ uint32_t pack_hi_lo(float a, float b, uint32_t& lo_out) {
    __half ha = __float2half_rn(a), hb = __float2half_rn(b);
    float la = a - __half2float(ha), lb = b - __half2float(hb);
    __half2 H = __halves2half2(ha, hb);
    __half2 L = __floats2half2_rn(la, lb);
    lo_out = *reinterpret_cast<uint32_t*>(&L);
    return *reinterpret_cast<uint32_t*>(&H);
}

__device__ __forceinline__ void mma16816(float* c, const uint32_t* a,
                                         uint32_t b0, uint32_t b1) {
    asm volatile(
        "mma.sync.aligned.m16n8k16.row.col.f32.f16.f16.f32 "
        "{%0,%1,%2,%3}, {%4,%5,%6,%7}, {%8,%9}, {%0,%1,%2,%3};"
        : "+f"(c[0]), "+f"(c[1]), "+f"(c[2]), "+f"(c[3])
        : "r"(a[0]), "r"(a[1]), "r"(a[2]), "r"(a[3]), "r"(b0), "r"(b1));
}

#define LDMATRIX_X4(r, addr) \
    asm volatile("ldmatrix.sync.aligned.m8n8.x4.shared.b16 {%0,%1,%2,%3}, [%4];" \
                 : "=r"((r)[0]), "=r"((r)[1]), "=r"((r)[2]), "=r"((r)[3]) \
                 : "r"(addr))

// ---------------------------------------------------------------------------
// Weight prep + index dtype sniff (merged launch).
// B fragments (hi/lo fp16) in mma.sync lane order.
// Logical B[k][n]: n<128 -> W1[n][k] (u), n>=128 -> W1[n-128][128+k] (v).
// Lane: t=lane&3, g=lane>>2; b0={B[ks*16+2t][n],B[..+1][n]}, b1 same at k+8,
// n = ntile*8+g.
// ---------------------------------------------------------------------------
__global__ void prep_kernel(const float* __restrict__ W1,
                            const int* __restrict__ idx32) {
    if (blockIdx.x == 0 && threadIdx.x < 32) {
        int lane = threadIdx.x;
        int nz = (idx32[2 * lane + 1] != 0) ? 1 : 0;
        unsigned m = __ballot_sync(0xffffffffu, nz);
        if (lane == 0) g_idx_is64 = (m == 0);
    }

    int i = blockIdx.x * blockDim.x + threadIdx.x;   // 0..8191
    if (i >= 8 * 32 * 32) return;
    int lane = i & 31;
    int nt   = (i >> 5) & 31;
    int ks   = i >> 10;
    int t = lane & 3, g = lane >> 2;
    int n = nt * 8 + g;
    int k0 = ks * 16 + 2 * t;

    int j    = n & 127;
    int koff = (n >> 7) << 7;   // 0 for u, 128 for v
    float w0 = W1[j * 256 + koff + k0];
    float w1 = W1[j * 256 + koff + k0 + 1];
    float w2 = W1[j * 256 + koff + k0 + 8];
    float w3 = W1[j * 256 + koff + k0 + 9];

    uint32_t l0, l1;
    uint32_t h0 = pack_hi_lo(w0, w1, l0);
    uint32_t h1 = pack_hi_lo(w2, w3, l1);
    g_Wfrag[i] = make_uint4(h0, h1, l0, l1);
}

// ---------------------------------------------------------------------------
// Node GEMM via mma.sync, 2-product split on W only:
//   D = Ah*Bh + Ah*Bl     (x-lo term dropped: adds ~2.8e-4 rel on h)
// CTA: 128 nodes x 256 outputs; 8 warps as 2(M) x 4(N); warp tile 64x64.
// x tile converted once to fp16 in static smem (272 B row stride,
// conflict-free ldmatrix). b1 folded into u; outputs stored fp16.
// ---------------------------------------------------------------------------
#define XH_STRIDE 136   // halves per row (272 B)

__global__ void __launch_bounds__(256, 1) node_gemm_mma(const float* __restrict__ x,
                                                        const float* __restrict__ b1,
                                                        int n_nodes) {
    __shared__ __align__(16) __half xh[128 * XH_STRIDE];   // 34816 B

    int tid = threadIdx.x;
    int n0  = blockIdx.x * 128;

    // Stage x tile as fp16: 128 rows x 32 float4 = 4096 loads.
    const float4* x4 = reinterpret_cast<const float4*>(x);
    #pragma unroll
    for (int rep = 0; rep < 16; rep++) {
        int tt = tid + rep * 256;      // 0..4095
        int row = tt >> 5, q = tt & 31;
        float4 v = make_float4(0.f, 0.f, 0.f, 0.f);
        if (n0 + row < n_nodes) v = x4[(size_t)(n0 + row) * 32 + q];
        __half2 h01 = __floats2half2_rn(v.x, v.y);
        __half2 h23 = __floats2half2_rn(v.z, v.w);
        int hofs = row * XH_STRIDE + q * 4;     // halves
        *reinterpret_cast<uint2*>(&xh[hofs]) =
            make_uint2(*reinterpret_cast<uint32_t*>(&h01),
                       *reinterpret_cast<uint32_t*>(&h23));
    }
    __syncthreads();

    int lane = tid & 31, wid = tid >> 5;
    int wM = wid >> 2;        // 0..1 : 64-row group
    int wN = wid & 3;         // 0..3 : 64-col group
    int t = lane & 3, g = lane >> 2;

    // ldmatrix lane addressing: lanes 0-15 -> rows (L&15), k-block 0;
    // lanes 16-31 -> same rows, k-block 1 (+8 halves = +16 B).
    int lrow = wM * 64 + (lane & 15);
    int lkb  = lane >> 4;
    uint32_t ph0 = smem_u32(xh) + (uint32_t)(lrow * XH_STRIDE + lkb * 8) * 2;

    float acc[4][8][4];
    #pragma unroll
    for (int mt = 0; mt < 4; mt++)
        #pragma unroll
        for (int j = 0; j < 8; j++)
            #pragma unroll
            for (int q = 0; q < 4; q++) acc[mt][j][q] = 0.f;

    #pragma unroll
    for (int ks = 0; ks < 8; ks++) {
        uint32_t ah[4][4];
        uint32_t ko = ks * 32;                       // 16 halves = 32 B per ks
        #pragma unroll
        for (int mt = 0; mt < 4; mt++)
            LDMATRIX_X4(ah[mt], ph0 + ko + (uint32_t)(mt * 16 * XH_STRIDE * 2));
        #pragma unroll
        for (int j = 0; j < 8; j++) {
            uint4 f = __ldg(&g_Wfrag[((ks * 32 + wN * 8 + j) << 5) + lane]);
            #pragma unroll
            for (int mt = 0; mt < 4; mt++) {
                mma16816(acc[mt][j], ah[mt], f.x, f.y);   // Ah*Bh
                mma16816(acc[mt][j], ah[mt], f.z, f.w);   // Ah*Bl
            }
        }
    }

    // Epilogue: cols wN*64 + j*8 + 2t. wN<2 -> u (+ b1 fold), wN>=2 -> v.
    __half* dstbase = reinterpret_cast<__half*>((wN < 2) ? g_u4 : g_v4);
    int colbase = (wN < 2) ? wN * 64 : (wN - 2) * 64;
    #pragma unroll
    for (int mt = 0; mt < 4; mt++) {
        int node0 = n0 + wM * 64 + mt * 16 + g;
        int node1 = node0 + 8;
        #pragma unroll
        for (int j = 0; j < 8; j++) {
            int col = colbase + j * 8 + 2 * t;
            float bb0 = 0.f, bb1 = 0.f;
            if (wN < 2) { float2 bv = *reinterpret_cast<const float2*>(&b1[col]);
                          bb0 = bv.x; bb1 = bv.y; }
            if (node0 < n_nodes)
                *reinterpret_cast<__half2*>(&dstbase[(size_t)node0 * D + col]) =
                    __floats2half2_rn(acc[mt][j][0] + bb0, acc[mt][j][1] + bb1);
            if (node1 < n_nodes)
                *reinterpret_cast<__half2*>(&dstbase[(size_t)node1 * D + col]) =
                    __floats2half2_rn(acc[mt][j][2] + bb0, acc[mt][j][3] + bb1);
        }
    }
}

// ---------------------------------------------------------------------------
// Edge phase: 8 lanes per edge, 4 edges per warp iteration.
// Lane: sub = lane>>3 (edge), fl = lane&7 (features [fl*16, fl*16+16)).
// fp16 add+relu+mul (w2 in fp16, 8 half2 regs), one fp16 pairwise add level,
// then cvt + fp32 tree; 3-stage shuffle reduce within 8 lanes.
// out[e] = sum_j relu(u'[s][j] + v[d][j]) * w2[j] + b2   (b1 already in u')
// ---------------------------------------------------------------------------
__device__ __forceinline__ float dot16h(uint4 uu, uint4 vv, const __half2* w2h) {
    const __half2* up = reinterpret_cast<const __half2*>(&uu);
    const __half2* vp = reinterpret_cast<const __half2*>(&vv);
    __half2 zero = __float2half2_rn(0.f);
    __half2 p0 = __hmul2(__hmax2(__hadd2(up[0], vp[0]), zero), w2h[0]);
    __half2 p1 = __hmul2(__hmax2(__hadd2(up[1], vp[1]), zero), w2h[1]);
    __half2 p2 = __hmul2(__hmax2(__hadd2(up[2], vp[2]), zero), w2h[2]);
    __half2 p3 = __hmul2(__hmax2(__hadd2(up[3], vp[3]), zero), w2h[3]);
    __half2 q0 = __hadd2(p0, p1);
    __half2 q1 = __hadd2(p2, p3);
    float2 f0 = __half22float2(q0);
    float2 f1 = __half22float2(q1);
    return (f0.x + f0.y) + (f1.x + f1.y);
}

__global__ void __launch_bounds__(128) edge_kernel(const int* __restrict__ idx32,
                                                   const float* __restrict__ W2,
                                                   const float* __restrict__ b2,
                                                   float* __restrict__ out,
                                                   int E) {
    int lane   = threadIdx.x & 31;
    int sub    = lane >> 3;        // edge within group
    int fl     = lane & 7;         // feature-lane
    int warp   = (int)((blockIdx.x * blockDim.x + threadIdx.x) >> 5);
    int nwarps = (int)((gridDim.x * blockDim.x) >> 5);

    int is64 = g_idx_is64;
    int mul  = is64 ? 2 : 1;
    int dofs = is64 ? 2 * E : E;

    // w2 for this lane's 16 features, as 8 half2 regs.
    __half2 w2h[8];
    #pragma unroll
    for (int q = 0; q < 4; q++) {
        float4 wv = reinterpret_cast<const float4*>(W2)[fl * 4 + q];
        w2h[2 * q + 0] = __floats2half2_rn(wv.x, wv.y);
        w2h[2 * q + 1] = __floats2half2_rn(wv.z, wv.w);
    }
    float b2s = __ldg(b2);

    int G = E >> 2;
    for (int gi = warp; gi < G; gi += nwarps) {
        int e = (gi << 2) + sub;
        int s = __ldg(&idx32[e * mul]);
        int d = __ldg(&idx32[dofs + e * mul]);

        const uint4* Ur = g_u4 + (size_t)s * 16 + fl * 2;
        const uint4* Vr = g_v4 + (size_t)d * 16 + fl * 2;
        uint4 u0 = __ldg(Ur), u1 = __ldg(Ur + 1);
        uint4 v0 = __ldg(Vr), v1 = __ldg(Vr + 1);

        float r = dot16h(u0, v0, w2h) + dot16h(u1, v1, w2h + 4);

        r += __shfl_xor_sync(0xffffffffu, r, 4);
        r += __shfl_xor_sync(0xffffffffu, r, 2);
        r += __shfl_xor_sync(0xffffffffu, r, 1);

        if (fl == 0) out[e] = r + b2s;   // 4 lanes -> coalesced 16 B
    }

    // tail (E % 4 edges), handled by warp 0
    int rem = E & 3;
    if (warp == 0 && sub < rem) {
        int e = (E & ~3) + sub;
        int s = __ldg(&idx32[e * mul]);
        int d = __ldg(&idx32[dofs + e * mul]);
        const uint4* Ur = g_u4 + (size_t)s * 16 + fl * 2;
        const uint4* Vr = g_v4 + (size_t)d * 16 + fl * 2;
        uint4 u0 = __ldg(Ur), u1 = __ldg(Ur + 1);
        uint4 v0 = __ldg(Vr), v1 = __ldg(Vr + 1);
        float r = dot16h(u0, v0, w2h) + dot16h(u1, v1, w2h + 4);
        r += __shfl_xor_sync(0xffffffffu, r, 4);
        r += __shfl_xor_sync(0xffffffffu, r, 2);
        r += __shfl_xor_sync(0xffffffffu, r, 1);
        if (fl == 0) out[e] = r + b2s;
    }
}

// ---------------------------------------------------------------------------
// Inputs: x [100000,128] f32, edge_index [2,E] (int32/int64 sniffed),
// W1 [128,256] f32, b1 [128] f32, W2 [1,128] f32, b2 [1] f32. Output: [E] f32.
// ---------------------------------------------------------------------------
extern "C" void kernel_launch(void* const* d_in, const int* in_sizes, int n_in,
                              void* d_out, int out_size) {
    const float* x    = (const float*)d_in[0];
    const int*   ei32 = (const int*)d_in[1];
    const float* W1   = (const float*)d_in[2];
    const float* b1   = (const float*)d_in[3];
    const float* W2   = (const float*)d_in[4];
    const float* b2   = (const float*)d_in[5];
    float* out = (float*)d_out;

    int n_nodes = in_sizes[0] / D;
    int E       = in_sizes[1] / 2;

    prep_kernel<<<32, 256>>>(W1, ei32);
    node_gemm_mma<<<(n_nodes + 127) / 128, 256>>>(x, b1, n_nodes);
    edge_kernel<<<4096, 128>>>(ei32, W2, b2, out, E);
}